// round 10
// baseline (speedup 1.0000x reference)
#include <cuda_runtime.h>
#include <cuda_fp16.h>
#include <cuda_bf16.h>
#include <math.h>
#include <stdint.h>

#define N_NODES 50000
#define N_EDGES 800000
#define IN_F    128
#define OUT_F   32
#define HEADS   4
#define HO      128            // HEADS * OUT_F
#define NEG_SLOPE 0.2f
#define EPS_F 1e-10f

#define SCAN_B 256
#define N_SCAN_BLOCKS ((N_NODES + SCAN_B - 1) / SCAN_B)   // 196

#define NB_GEMM ((N_NODES + 127) / 128)                   // 391
#define NB_HIST ((N_EDGES + 255) / 256)                   // 3125

// smem: 4 planes of [128][136] bf16 (Xhi, Xlo, Whi, Wlo)
#define SM_STRIDE 136
#define SM_PLANE  (128 * SM_STRIDE)                       // halves per plane
#define SMEM_GEMM_BYTES (4 * SM_PLANE * 2)                // 139264
#define W_UINT4   (2 * SM_PLANE / 8)                      // 4352 uint4 in W image

// ---------------- scratch (static device allocations) ----------------------
__device__ __half g_h16[N_NODES * HO];     // projected features, fp16 [N, H*O]
__device__ float g_es[N_NODES * HEADS];    // per-node src logits (fp32)
__device__ float g_ed[N_NODES * HEADS];    // per-node dst logits (fp32)
__device__ __align__(16) __nv_bfloat16 g_Wsplit[2 * SM_PLANE]; // Whi|Wlo smem image
__device__ int   g_count[N_NODES];         // zeroed at load; re-zeroed by scan
__device__ int   g_offset[N_NODES + 1];
__device__ int   g_cursor[N_NODES];
__device__ int   g_srcsorted[N_EDGES];
// decoupled-lookback state (zeroed at load; re-zeroed by k_scatter)
__device__ int                g_ticket;
__device__ unsigned long long g_state[N_SCAN_BLOCKS];   // (sum<<2)|status

struct __align__(8) h2x2 { __half2 a, b; };

// ---------------- bf16 mma helper ------------------------------------------
__device__ __forceinline__ void mma_bf16(float c[4],
    uint32_t a0, uint32_t a1, uint32_t a2, uint32_t a3,
    uint32_t b0, uint32_t b1)
{
    asm volatile(
        "mma.sync.aligned.m16n8k16.row.col.f32.bf16.bf16.f32 "
        "{%0,%1,%2,%3},{%4,%5,%6,%7},{%8,%9},{%0,%1,%2,%3};\n"
        : "+f"(c[0]), "+f"(c[1]), "+f"(c[2]), "+f"(c[3])
        : "r"(a0), "r"(a1), "r"(a2), "r"(a3), "r"(b0), "r"(b1));
}

// ---------------- K0: split W once into the swizzled smem image -------------
// W [head][k][o] -> g_Wsplit: plane0=Whi, plane1=Wlo, [n][ks] with
// ks = k ^ ((n&3)<<4), row stride 136.
__global__ void k_prep(const float* __restrict__ W) {
    int idx = blockIdx.x * blockDim.x + threadIdx.x;     // 0..16383
    if (idx >= HEADS * IN_F * OUT_F) return;
    int o = idx & 31;
    int k = (idx >> 5) & 127;
    int n = (idx >> 12) * 32 + o;
    int ks = k ^ ((n & 3) << 4);
    float v = W[idx];
    __nv_bfloat16 hb = __float2bfloat16_rn(v);
    __nv_bfloat16 lb = __float2bfloat16_rn(v - __bfloat162float(hb));
    g_Wsplit[n * SM_STRIDE + ks] = hb;
    g_Wsplit[SM_PLANE + n * SM_STRIDE + ks] = lb;
}

// ---------------- K1: bf16x3 tensor GEMM h = x @ Wc + fused logits ----------
// 512 thr = 16 warps in 8x2 grid, warp tile 16x64. Whole K staged once.
// W planes bulk-copied from the pre-split global image (L2-resident).
__global__ void __launch_bounds__(512) k_gemm(
    const float* __restrict__ x,
    const float* __restrict__ a_src,
    const float* __restrict__ a_dst)
{
    extern __shared__ __nv_bfloat16 sm[];
    __nv_bfloat16* Xhi = sm;
    __nv_bfloat16* Xlo = sm + SM_PLANE;
    __nv_bfloat16* Whi = sm + 2 * SM_PLANE;   // [n][k], swizzled
    __nv_bfloat16* Wlo = sm + 3 * SM_PLANE;

    int tid  = threadIdx.x;
    int w    = tid >> 5;
    int lane = tid & 31;
    int g    = lane >> 2;
    int t    = lane & 3;
    int wm   = w >> 1;       // warp row 0..7 (16 rows each)
    int wn   = w & 1;        // warp col 0..1 (64 cols each)
    int m0   = blockIdx.x * 128;

    // ---- stage X (128 rows x 128 k), split to bf16 hi/lo, STS.64 ----
    #pragma unroll
    for (int i = 0; i < 8; ++i) {
        int f = tid + i * 512;          // float4 id, 0..4095
        int r = f >> 5;
        int c = (f & 31) * 4;
        int grow = m0 + r;
        float4 v = make_float4(0.f, 0.f, 0.f, 0.f);
        if (grow < N_NODES) v = *(const float4*)&x[grow * IN_F + c];
        float vv[4] = {v.x, v.y, v.z, v.w};
        __nv_bfloat16 hb[4], lb[4];
        #pragma unroll
        for (int j = 0; j < 4; ++j) {
            hb[j] = __float2bfloat16_rn(vv[j]);
            lb[j] = __float2bfloat16_rn(vv[j] - __bfloat162float(hb[j]));
        }
        __nv_bfloat162 ph0(hb[0], hb[1]), ph1(hb[2], hb[3]);
        __nv_bfloat162 pl0(lb[0], lb[1]), pl1(lb[2], lb[3]);
        uint2 uh = make_uint2(reinterpret_cast<uint32_t&>(ph0),
                              reinterpret_cast<uint32_t&>(ph1));
        uint2 ul = make_uint2(reinterpret_cast<uint32_t&>(pl0),
                              reinterpret_cast<uint32_t&>(pl1));
        *(uint2*)&Xhi[r * SM_STRIDE + c] = uh;
        *(uint2*)&Xlo[r * SM_STRIDE + c] = ul;
    }
    // ---- bulk-copy the pre-split W image (70 KB, L2-resident) ----
    {
        const uint4* src = (const uint4*)g_Wsplit;
        uint4* dst = (uint4*)Whi;
        #pragma unroll
        for (int i = 0; i < 9; ++i) {
            int f = tid + i * 512;
            if (f < W_UINT4) dst[f] = src[f];
        }
    }
    __syncthreads();

    float C[8][4];
    #pragma unroll
    for (int nt = 0; nt < 8; ++nt)
        #pragma unroll
        for (int j = 0; j < 4; ++j) C[nt][j] = 0.0f;

    int r0 = wm * 16 + g;

    // ---- mainloop: 8 k-chunks of 16; LDS + MMA only ----
    #pragma unroll
    for (int kc = 0; kc < 8; ++kc) {
        int kw = kc * 8 + t;            // uint32 (bf16x2) index
        uint32_t axh[4], axl[4];
        {
            const uint32_t* ph0 = (const uint32_t*)(Xhi + r0 * SM_STRIDE);
            const uint32_t* ph8 = (const uint32_t*)(Xhi + (r0 + 8) * SM_STRIDE);
            const uint32_t* pl0 = (const uint32_t*)(Xlo + r0 * SM_STRIDE);
            const uint32_t* pl8 = (const uint32_t*)(Xlo + (r0 + 8) * SM_STRIDE);
            axh[0] = ph0[kw];     axh[1] = ph8[kw];
            axh[2] = ph0[kw + 4]; axh[3] = ph8[kw + 4];
            axl[0] = pl0[kw];     axl[1] = pl8[kw];
            axl[2] = pl0[kw + 4]; axl[3] = pl8[kw + 4];
        }
        #pragma unroll
        for (int nt = 0; nt < 8; ++nt) {
            int n = wn * 64 + nt * 8 + g;
            int kws = kw ^ ((n & 3) << 3);     // swizzled word index
            const uint32_t* qh = (const uint32_t*)(Whi + n * SM_STRIDE);
            const uint32_t* ql = (const uint32_t*)(Wlo + n * SM_STRIDE);
            uint32_t bh0 = qh[kws], bh1 = qh[kws + 4];
            uint32_t bl0 = ql[kws], bl1 = ql[kws + 4];
            mma_bf16(C[nt], axh[0], axh[1], axh[2], axh[3], bh0, bh1);
            mma_bf16(C[nt], axh[0], axh[1], axh[2], axh[3], bl0, bl1);
            mma_bf16(C[nt], axl[0], axl[1], axl[2], axl[3], bh0, bh1);
        }
    }

    // ---- epilogue: fp16 h store + fused per-head logits ----
    int row0 = m0 + r0;
    int row1 = row0 + 8;
    float psA[2], pdA[2], psB[2], pdB[2];
    #pragma unroll
    for (int hl = 0; hl < 2; ++hl)
        psA[hl] = pdA[hl] = psB[hl] = pdB[hl] = 0.f;

    #pragma unroll
    for (int nt = 0; nt < 8; ++nt) {
        int hl = nt >> 2;
        int c0 = wn * 64 + nt * 8 + 2 * t;
        float as0 = a_src[c0], as1 = a_src[c0 + 1];
        float ad0 = a_dst[c0], ad1 = a_dst[c0 + 1];
        psA[hl] += C[nt][0] * as0 + C[nt][1] * as1;
        pdA[hl] += C[nt][0] * ad0 + C[nt][1] * ad1;
        psB[hl] += C[nt][2] * as0 + C[nt][3] * as1;
        pdB[hl] += C[nt][2] * ad0 + C[nt][3] * ad1;
        if (row0 < N_NODES)
            *(__half2*)&g_h16[row0 * HO + c0] =
                __floats2half2_rn(C[nt][0], C[nt][1]);
        if (row1 < N_NODES)
            *(__half2*)&g_h16[row1 * HO + c0] =
                __floats2half2_rn(C[nt][2], C[nt][3]);
    }
    #pragma unroll
    for (int hl = 0; hl < 2; ++hl) {
        psA[hl] += __shfl_xor_sync(0xffffffffu, psA[hl], 1);
        psA[hl] += __shfl_xor_sync(0xffffffffu, psA[hl], 2);
        pdA[hl] += __shfl_xor_sync(0xffffffffu, pdA[hl], 1);
        pdA[hl] += __shfl_xor_sync(0xffffffffu, pdA[hl], 2);
        psB[hl] += __shfl_xor_sync(0xffffffffu, psB[hl], 1);
        psB[hl] += __shfl_xor_sync(0xffffffffu, psB[hl], 2);
        pdB[hl] += __shfl_xor_sync(0xffffffffu, pdB[hl], 1);
        pdB[hl] += __shfl_xor_sync(0xffffffffu, pdB[hl], 2);
    }
    if (t == 0) {
        if (row0 < N_NODES) {
            *(float2*)&g_es[row0 * HEADS + wn * 2] = make_float2(psA[0], psA[1]);
            *(float2*)&g_ed[row0 * HEADS + wn * 2] = make_float2(pdA[0], pdA[1]);
        }
        if (row1 < N_NODES) {
            *(float2*)&g_es[row1 * HEADS + wn * 2] = make_float2(psB[0], psB[1]);
            *(float2*)&g_ed[row1 * HEADS + wn * 2] = make_float2(pdB[0], pdB[1]);
        }
    }
}

// ---------------- K2: degree histogram (side stream) ------------------------
__global__ void k_hist(const int* __restrict__ ei) {
    int e = blockIdx.x * blockDim.x + threadIdx.x;
    if (e < N_EDGES) atomicAdd(&g_count[ei[N_EDGES + e]], 1);
}

// ---------------- K3: single-kernel decoupled-lookback scan ------------------
__global__ void __launch_bounds__(SCAN_B) k_scanlb() {
    __shared__ int warp_sums[8];
    __shared__ int sh_bid;
    __shared__ long long sh_prefix;

    if (threadIdx.x == 0) sh_bid = atomicAdd(&g_ticket, 1);
    __syncthreads();
    int bid = sh_bid;

    int i = bid * SCAN_B + threadIdx.x;
    int lane = threadIdx.x & 31, wid = threadIdx.x >> 5;
    int c = (i < N_NODES) ? g_count[i] : 0;
    if (i < N_NODES) g_count[i] = 0;             // restore for next replay
    int v = c;
    #pragma unroll
    for (int d = 1; d < 32; d <<= 1) {
        int u = __shfl_up_sync(0xffffffffu, v, d);
        if (lane >= d) v += u;
    }
    if (lane == 31) warp_sums[wid] = v;
    __syncthreads();
    if (wid == 0) {
        int s = (lane < 8) ? warp_sums[lane] : 0;
        #pragma unroll
        for (int d = 1; d < 8; d <<= 1) {
            int u = __shfl_up_sync(0xffffffffu, s, d);
            if (lane >= d) s += u;
        }
        if (lane < 8) warp_sums[lane] = s;
    }
    __syncthreads();
    int incl = v + (wid ? warp_sums[wid - 1] : 0);
    long long T = warp_sums[7];

    if (threadIdx.x == 0) {
        if (bid == 0) {
            atomicExch(&g_state[0], ((unsigned long long)T << 2) | 2ULL);
            sh_prefix = 0;
        } else {
            atomicExch(&g_state[bid], ((unsigned long long)T << 2) | 1ULL);
            long long exc = 0;
            int pred = bid - 1;
            while (pred >= 0) {
                unsigned long long s;
                do { s = atomicAdd(&g_state[pred], 0ULL); } while ((s & 3ULL) == 0ULL);
                exc += (long long)(s >> 2);
                if ((s & 3ULL) == 2ULL) break;
                --pred;
            }
            atomicExch(&g_state[bid], ((unsigned long long)(exc + T) << 2) | 2ULL);
            sh_prefix = exc;
        }
    }
    __syncthreads();
    int pre = (int)sh_prefix;
    if (i < N_NODES) {
        int off = pre + incl - c;
        g_offset[i] = off;
        g_cursor[i] = off;
    }
    if (i == 0) g_offset[N_NODES] = N_EDGES;
}

// ---------------- K4: bucket edges by dst + reset lookback state -------------
__global__ void k_scatter(const int* __restrict__ ei) {
    if (blockIdx.x == 0) {
        if (threadIdx.x < N_SCAN_BLOCKS) g_state[threadIdx.x] = 0ULL;
        if (threadIdx.x == 0) g_ticket = 0;
    }
    int e = blockIdx.x * blockDim.x + threadIdx.x;
    if (e < N_EDGES) {
        int src = ei[e];
        int dst = ei[N_EDGES + e];
        int pos = atomicAdd(&g_cursor[dst], 1);
        g_srcsorted[pos] = src;
    }
}

// ---------------- K5: softmax + aggregation (warp per node, ILP-4) -----------
__global__ void __launch_bounds__(256) k_aggregate(float* __restrict__ out)
{
    int warp = threadIdx.x >> 5;
    int lane = threadIdx.x & 31;
    int n = blockIdx.x * 8 + warp;
    if (n >= N_NODES) return;

    int head = lane >> 3;
    int beg = g_offset[n];
    int end = g_offset[n + 1];

    float4 edn = *(const float4*)&g_ed[n * HEADS];
    float edh = (head == 0) ? edn.x : (head == 1) ? edn.y : (head == 2) ? edn.z : edn.w;

    float4 acc0 = make_float4(0.f, 0.f, 0.f, 0.f);
    float4 acc1 = make_float4(0.f, 0.f, 0.f, 0.f);
    float  ssum = 0.f;
    int e = beg;
    for (; e + 4 <= end; e += 4) {
        int s0 = g_srcsorted[e];
        int s1 = g_srcsorted[e + 1];
        int s2 = g_srcsorted[e + 2];
        int s3 = g_srcsorted[e + 3];
        float ev0 = g_es[s0 * HEADS + head] + edh;
        float ev1 = g_es[s1 * HEADS + head] + edh;
        float ev2 = g_es[s2 * HEADS + head] + edh;
        float ev3 = g_es[s3 * HEADS + head] + edh;
        h2x2 v0 = *(const h2x2*)&g_h16[s0 * HO + lane * 4];
        h2x2 v1 = *(const h2x2*)&g_h16[s1 * HO + lane * 4];
        h2x2 v2 = *(const h2x2*)&g_h16[s2 * HO + lane * 4];
        h2x2 v3 = *(const h2x2*)&g_h16[s3 * HO + lane * 4];
        ev0 = ev0 >= 0.f ? ev0 : NEG_SLOPE * ev0;
        ev1 = ev1 >= 0.f ? ev1 : NEG_SLOPE * ev1;
        ev2 = ev2 >= 0.f ? ev2 : NEG_SLOPE * ev2;
        ev3 = ev3 >= 0.f ? ev3 : NEG_SLOPE * ev3;
        float w0 = __expf(ev0);
        float w1 = __expf(ev1);
        float w2 = __expf(ev2);
        float w3 = __expf(ev3);
        ssum += (w0 + w1) + (w2 + w3);
        float2 f0a = __half22float2(v0.a), f0b = __half22float2(v0.b);
        float2 f1a = __half22float2(v1.a), f1b = __half22float2(v1.b);
        float2 f2a = __half22float2(v2.a), f2b = __half22float2(v2.b);
        float2 f3a = __half22float2(v3.a), f3b = __half22float2(v3.b);
        acc0.x = fmaf(w0, f0a.x, acc0.x); acc0.y = fmaf(w0, f0a.y, acc0.y);
        acc0.z = fmaf(w0, f0b.x, acc0.z); acc0.w = fmaf(w0, f0b.y, acc0.w);
        acc1.x = fmaf(w1, f1a.x, acc1.x); acc1.y = fmaf(w1, f1a.y, acc1.y);
        acc1.z = fmaf(w1, f1b.x, acc1.z); acc1.w = fmaf(w1, f1b.y, acc1.w);
        acc0.x = fmaf(w2, f2a.x, acc0.x); acc0.y = fmaf(w2, f2a.y, acc0.y);
        acc0.z = fmaf(w2, f2b.x, acc0.z); acc0.w = fmaf(w2, f2b.y, acc0.w);
        acc1.x = fmaf(w3, f3a.x, acc1.x); acc1.y = fmaf(w3, f3a.y, acc1.y);
        acc1.z = fmaf(w3, f3b.x, acc1.z); acc1.w = fmaf(w3, f3b.y, acc1.w);
    }
    for (; e < end; ++e) {
        int s0 = g_srcsorted[e];
        float ev0 = g_es[s0 * HEADS + head] + edh;
        h2x2 v0 = *(const h2x2*)&g_h16[s0 * HO + lane * 4];
        ev0 = ev0 >= 0.f ? ev0 : NEG_SLOPE * ev0;
        float w0 = __expf(ev0);
        ssum += w0;
        float2 f0a = __half22float2(v0.a), f0b = __half22float2(v0.b);
        acc0.x = fmaf(w0, f0a.x, acc0.x); acc0.y = fmaf(w0, f0a.y, acc0.y);
        acc0.z = fmaf(w0, f0b.x, acc0.z); acc0.w = fmaf(w0, f0b.y, acc0.w);
    }
    float inv = 1.0f / (ssum + EPS_F);
    float4 r = make_float4((acc0.x + acc1.x) * inv, (acc0.y + acc1.y) * inv,
                           (acc0.z + acc1.z) * inv, (acc0.w + acc1.w) * inv);
    *(float4*)&out[n * HO + lane * 4] = r;
}

// ---------------- launch: fork CSR chain onto a side stream ------------------
extern "C" void kernel_launch(void* const* d_in, const int* in_sizes, int n_in,
                              void* d_out, int out_size)
{
    const float* x     = (const float*)d_in[0];
    const int*   ei    = (const int*)  d_in[1];
    const float* W     = (const float*)d_in[2];
    const float* a_src = (const float*)d_in[3];
    const float* a_dst = (const float*)d_in[4];
    float* out = (float*)d_out;

    cudaFuncSetAttribute(k_gemm, cudaFuncAttributeMaxDynamicSharedMemorySize,
                         SMEM_GEMM_BYTES);

    cudaStream_t s1;
    cudaStreamCreateWithFlags(&s1, cudaStreamNonBlocking);
    cudaEvent_t ev0, ev1;
    cudaEventCreateWithFlags(&ev0, cudaEventDisableTiming);
    cudaEventCreateWithFlags(&ev1, cudaEventDisableTiming);

    cudaEventRecord(ev0, 0);
    cudaStreamWaitEvent(s1, ev0, 0);

    // side chain: CSR build (independent of GEMM)
    k_hist   <<<NB_HIST, 256, 0, s1>>>(ei);
    k_scanlb <<<N_SCAN_BLOCKS, SCAN_B, 0, s1>>>();
    k_scatter<<<(N_EDGES + 255) / 256, 256, 0, s1>>>(ei);
    cudaEventRecord(ev1, s1);

    // main stream: W pre-split, then projection GEMM (+logits)
    k_prep<<<(HEADS * IN_F * OUT_F + 255) / 256, 256>>>(W);
    k_gemm<<<NB_GEMM, 512, SMEM_GEMM_BYTES>>>(x, a_src, a_dst);

    // join, then aggregate
    cudaStreamWaitEvent(0, ev1, 0);
    k_aggregate<<<(N_NODES + 7) / 8, 256>>>(out);

    cudaEventDestroy(ev0);
    cudaEventDestroy(ev1);
    cudaStreamDestroy(s1);
}

// round 11
// speedup vs baseline: 1.0337x; 1.0337x over previous
#include <cuda_runtime.h>
#include <cuda_fp16.h>
#include <cuda_bf16.h>
#include <math.h>
#include <stdint.h>

#define N_NODES 50000
#define N_EDGES 800000
#define IN_F    128
#define OUT_F   32
#define HEADS   4
#define HO      128            // HEADS * OUT_F
#define NEG_SLOPE 0.2f
#define EPS_F 1e-10f

#define SCAN_B 256
#define N_SCAN_BLOCKS ((N_NODES + SCAN_B - 1) / SCAN_B)   // 196

#define BM 256
#define NB_GEMM ((N_NODES + BM - 1) / BM)                 // 196
#define NB_HIST ((N_EDGES + 255) / 256)                   // 3125

// smem: X planes [256][136] bf16 (hi/lo) + W planes [128][136] bf16 (hi/lo)
#define SM_STRIDE 136
#define SMX_PLANE (256 * SM_STRIDE)                       // 34816 halves
#define SMW_PLANE (128 * SM_STRIDE)                       // 17408 halves
#define SMEM_GEMM_BYTES ((2 * SMX_PLANE + 2 * SMW_PLANE) * 2)   // 208896
#define W_UINT4   (2 * SMW_PLANE * 2 / 16)                // 4352 uint4

// ---------------- scratch (static device allocations) ----------------------
__device__ __half g_h16[N_NODES * HO];     // projected features, fp16 [N, H*O]
__device__ float g_es[N_NODES * HEADS];    // per-node src logits (fp32)
__device__ float g_ed[N_NODES * HEADS];    // per-node dst logits (fp32)
__device__ __align__(16) __nv_bfloat16 g_Wsplit[2 * SMW_PLANE]; // Whi|Wlo image
__device__ int   g_count[N_NODES];         // zeroed at load; re-zeroed by scan
__device__ int   g_offset[N_NODES + 1];
__device__ int   g_cursor[N_NODES];
__device__ int   g_srcsorted[N_EDGES];
// decoupled-lookback state (zeroed at load; re-zeroed by k_scatter)
__device__ int                g_ticket;
__device__ unsigned long long g_state[N_SCAN_BLOCKS];   // (sum<<2)|status

// ---------------- bf16 mma helper ------------------------------------------
__device__ __forceinline__ void mma_bf16(float c[4],
    uint32_t a0, uint32_t a1, uint32_t a2, uint32_t a3,
    uint32_t b0, uint32_t b1)
{
    asm volatile(
        "mma.sync.aligned.m16n8k16.row.col.f32.bf16.bf16.f32 "
        "{%0,%1,%2,%3},{%4,%5,%6,%7},{%8,%9},{%0,%1,%2,%3};\n"
        : "+f"(c[0]), "+f"(c[1]), "+f"(c[2]), "+f"(c[3])
        : "r"(a0), "r"(a1), "r"(a2), "r"(a3), "r"(b0), "r"(b1));
}

// ---------------- K0: split W once into the swizzled smem image -------------
__global__ void k_prep(const float* __restrict__ W) {
    int idx = blockIdx.x * blockDim.x + threadIdx.x;     // 0..16383
    if (idx >= HEADS * IN_F * OUT_F) return;
    int o = idx & 31;
    int k = (idx >> 5) & 127;
    int n = (idx >> 12) * 32 + o;
    int ks = k ^ ((n & 3) << 4);
    float v = W[idx];
    __nv_bfloat16 hb = __float2bfloat16_rn(v);
    __nv_bfloat16 lb = __float2bfloat16_rn(v - __bfloat162float(hb));
    g_Wsplit[n * SM_STRIDE + ks] = hb;
    g_Wsplit[SMW_PLANE + n * SM_STRIDE + ks] = lb;
}

// ---------------- K1: bf16x3 tensor GEMM h = x @ Wc + fused logits ----------
// 512 thr = 16 warps in 8x2 grid; block tile 256x128; warp tile 32x64.
__global__ void __launch_bounds__(512) k_gemm(
    const float* __restrict__ x,
    const float* __restrict__ a_src,
    const float* __restrict__ a_dst)
{
    extern __shared__ __nv_bfloat16 sm[];
    __nv_bfloat16* Xhi = sm;
    __nv_bfloat16* Xlo = sm + SMX_PLANE;
    __nv_bfloat16* Whi = sm + 2 * SMX_PLANE;              // [n][k], swizzled
    __nv_bfloat16* Wlo = sm + 2 * SMX_PLANE + SMW_PLANE;

    int tid  = threadIdx.x;
    int w    = tid >> 5;
    int lane = tid & 31;
    int g    = lane >> 2;
    int t    = lane & 3;
    int wm   = w >> 1;       // warp row 0..7 (32 rows each)
    int wn   = w & 1;        // warp col 0..1 (64 cols each)
    int m0   = blockIdx.x * BM;

    // ---- stage X (256 rows x 128 k), split to bf16 hi/lo ----
    #pragma unroll
    for (int i = 0; i < 16; ++i) {
        int f = tid + i * 512;          // float4 id, 0..8191
        int r = f >> 5;
        int c = (f & 31) * 4;
        int grow = m0 + r;
        float4 v = make_float4(0.f, 0.f, 0.f, 0.f);
        if (grow < N_NODES) v = *(const float4*)&x[grow * IN_F + c];
        float vv[4] = {v.x, v.y, v.z, v.w};
        __nv_bfloat16 hb[4], lb[4];
        #pragma unroll
        for (int j = 0; j < 4; ++j) {
            hb[j] = __float2bfloat16_rn(vv[j]);
            lb[j] = __float2bfloat16_rn(vv[j] - __bfloat162float(hb[j]));
        }
        __nv_bfloat162 ph0(hb[0], hb[1]), ph1(hb[2], hb[3]);
        __nv_bfloat162 pl0(lb[0], lb[1]), pl1(lb[2], lb[3]);
        uint2 uh = make_uint2(reinterpret_cast<uint32_t&>(ph0),
                              reinterpret_cast<uint32_t&>(ph1));
        uint2 ul = make_uint2(reinterpret_cast<uint32_t&>(pl0),
                              reinterpret_cast<uint32_t&>(pl1));
        *(uint2*)&Xhi[r * SM_STRIDE + c] = uh;
        *(uint2*)&Xlo[r * SM_STRIDE + c] = ul;
    }
    // ---- bulk-copy the pre-split W image (70 KB, L2-resident) ----
    {
        const uint4* src = (const uint4*)g_Wsplit;
        uint4* dst = (uint4*)Whi;
        #pragma unroll
        for (int i = 0; i < 9; ++i) {
            int f = tid + i * 512;
            if (f < W_UINT4) dst[f] = src[f];
        }
    }
    __syncthreads();

    float C[2][8][4];
    #pragma unroll
    for (int ms = 0; ms < 2; ++ms)
        #pragma unroll
        for (int nt = 0; nt < 8; ++nt)
            #pragma unroll
            for (int j = 0; j < 4; ++j) C[ms][nt][j] = 0.0f;

    // ---- mainloop: 8 k-chunks of 16; LDS + MMA only ----
    #pragma unroll
    for (int kc = 0; kc < 8; ++kc) {
        int kw = kc * 8 + t;            // uint32 (bf16x2) index
        uint32_t axh[2][4], axl[2][4];
        #pragma unroll
        for (int ms = 0; ms < 2; ++ms) {
            int r0 = wm * 32 + ms * 16 + g;
            const uint32_t* ph0 = (const uint32_t*)(Xhi + r0 * SM_STRIDE);
            const uint32_t* ph8 = (const uint32_t*)(Xhi + (r0 + 8) * SM_STRIDE);
            const uint32_t* pl0 = (const uint32_t*)(Xlo + r0 * SM_STRIDE);
            const uint32_t* pl8 = (const uint32_t*)(Xlo + (r0 + 8) * SM_STRIDE);
            axh[ms][0] = ph0[kw];     axh[ms][1] = ph8[kw];
            axh[ms][2] = ph0[kw + 4]; axh[ms][3] = ph8[kw + 4];
            axl[ms][0] = pl0[kw];     axl[ms][1] = pl8[kw];
            axl[ms][2] = pl0[kw + 4]; axl[ms][3] = pl8[kw + 4];
        }
        #pragma unroll
        for (int nt = 0; nt < 8; ++nt) {
            int n = wn * 64 + nt * 8 + g;
            int kws = kw ^ ((n & 3) << 3);     // swizzled word index
            const uint32_t* qh = (const uint32_t*)(Whi + n * SM_STRIDE);
            const uint32_t* ql = (const uint32_t*)(Wlo + n * SM_STRIDE);
            uint32_t bh0 = qh[kws], bh1 = qh[kws + 4];
            uint32_t bl0 = ql[kws], bl1 = ql[kws + 4];
            #pragma unroll
            for (int ms = 0; ms < 2; ++ms) {
                mma_bf16(C[ms][nt], axh[ms][0], axh[ms][1], axh[ms][2], axh[ms][3], bh0, bh1);
                mma_bf16(C[ms][nt], axh[ms][0], axh[ms][1], axh[ms][2], axh[ms][3], bl0, bl1);
                mma_bf16(C[ms][nt], axl[ms][0], axl[ms][1], axl[ms][2], axl[ms][3], bh0, bh1);
            }
        }
    }

    // ---- epilogue: fp16 h store + fused per-head logits ----
    float psA[2][2], pdA[2][2], psB[2][2], pdB[2][2];
    #pragma unroll
    for (int ms = 0; ms < 2; ++ms)
        #pragma unroll
        for (int hl = 0; hl < 2; ++hl)
            psA[ms][hl] = pdA[ms][hl] = psB[ms][hl] = pdB[ms][hl] = 0.f;

    #pragma unroll
    for (int nt = 0; nt < 8; ++nt) {
        int hl = nt >> 2;
        int c0 = wn * 64 + nt * 8 + 2 * t;
        float as0 = a_src[c0], as1 = a_src[c0 + 1];
        float ad0 = a_dst[c0], ad1 = a_dst[c0 + 1];
        #pragma unroll
        for (int ms = 0; ms < 2; ++ms) {
            int row0 = m0 + wm * 32 + ms * 16 + g;
            psA[ms][hl] += C[ms][nt][0] * as0 + C[ms][nt][1] * as1;
            pdA[ms][hl] += C[ms][nt][0] * ad0 + C[ms][nt][1] * ad1;
            psB[ms][hl] += C[ms][nt][2] * as0 + C[ms][nt][3] * as1;
            pdB[ms][hl] += C[ms][nt][2] * ad0 + C[ms][nt][3] * ad1;
            if (row0 < N_NODES)
                *(__half2*)&g_h16[row0 * HO + c0] =
                    __floats2half2_rn(C[ms][nt][0], C[ms][nt][1]);
            if (row0 + 8 < N_NODES)
                *(__half2*)&g_h16[(row0 + 8) * HO + c0] =
                    __floats2half2_rn(C[ms][nt][2], C[ms][nt][3]);
        }
    }
    #pragma unroll
    for (int ms = 0; ms < 2; ++ms)
        #pragma unroll
        for (int hl = 0; hl < 2; ++hl) {
            psA[ms][hl] += __shfl_xor_sync(0xffffffffu, psA[ms][hl], 1);
            psA[ms][hl] += __shfl_xor_sync(0xffffffffu, psA[ms][hl], 2);
            pdA[ms][hl] += __shfl_xor_sync(0xffffffffu, pdA[ms][hl], 1);
            pdA[ms][hl] += __shfl_xor_sync(0xffffffffu, pdA[ms][hl], 2);
            psB[ms][hl] += __shfl_xor_sync(0xffffffffu, psB[ms][hl], 1);
            psB[ms][hl] += __shfl_xor_sync(0xffffffffu, psB[ms][hl], 2);
            pdB[ms][hl] += __shfl_xor_sync(0xffffffffu, pdB[ms][hl], 1);
            pdB[ms][hl] += __shfl_xor_sync(0xffffffffu, pdB[ms][hl], 2);
        }
    if (t == 0) {
        #pragma unroll
        for (int ms = 0; ms < 2; ++ms) {
            int row0 = m0 + wm * 32 + ms * 16 + g;
            int row1 = row0 + 8;
            if (row0 < N_NODES) {
                *(float2*)&g_es[row0 * HEADS + wn * 2] = make_float2(psA[ms][0], psA[ms][1]);
                *(float2*)&g_ed[row0 * HEADS + wn * 2] = make_float2(pdA[ms][0], pdA[ms][1]);
            }
            if (row1 < N_NODES) {
                *(float2*)&g_es[row1 * HEADS + wn * 2] = make_float2(psB[ms][0], psB[ms][1]);
                *(float2*)&g_ed[row1 * HEADS + wn * 2] = make_float2(pdB[ms][0], pdB[ms][1]);
            }
        }
    }
}

// ---------------- K2: degree histogram (side stream) ------------------------
__global__ void k_hist(const int* __restrict__ ei) {
    int e = blockIdx.x * blockDim.x + threadIdx.x;
    if (e < N_EDGES) atomicAdd(&g_count[ei[N_EDGES + e]], 1);
}

// ---------------- K3: single-kernel decoupled-lookback scan ------------------
__global__ void __launch_bounds__(SCAN_B) k_scanlb() {
    __shared__ int warp_sums[8];
    __shared__ int sh_bid;
    __shared__ long long sh_prefix;

    if (threadIdx.x == 0) sh_bid = atomicAdd(&g_ticket, 1);
    __syncthreads();
    int bid = sh_bid;

    int i = bid * SCAN_B + threadIdx.x;
    int lane = threadIdx.x & 31, wid = threadIdx.x >> 5;
    int c = (i < N_NODES) ? g_count[i] : 0;
    if (i < N_NODES) g_count[i] = 0;             // restore for next replay
    int v = c;
    #pragma unroll
    for (int d = 1; d < 32; d <<= 1) {
        int u = __shfl_up_sync(0xffffffffu, v, d);
        if (lane >= d) v += u;
    }
    if (lane == 31) warp_sums[wid] = v;
    __syncthreads();
    if (wid == 0) {
        int s = (lane < 8) ? warp_sums[lane] : 0;
        #pragma unroll
        for (int d = 1; d < 8; d <<= 1) {
            int u = __shfl_up_sync(0xffffffffu, s, d);
            if (lane >= d) s += u;
        }
        if (lane < 8) warp_sums[lane] = s;
    }
    __syncthreads();
    int incl = v + (wid ? warp_sums[wid - 1] : 0);
    long long T = warp_sums[7];

    if (threadIdx.x == 0) {
        if (bid == 0) {
            atomicExch(&g_state[0], ((unsigned long long)T << 2) | 2ULL);
            sh_prefix = 0;
        } else {
            atomicExch(&g_state[bid], ((unsigned long long)T << 2) | 1ULL);
            long long exc = 0;
            int pred = bid - 1;
            while (pred >= 0) {
                unsigned long long s;
                do { s = atomicAdd(&g_state[pred], 0ULL); } while ((s & 3ULL) == 0ULL);
                exc += (long long)(s >> 2);
                if ((s & 3ULL) == 2ULL) break;
                --pred;
            }
            atomicExch(&g_state[bid], ((unsigned long long)(exc + T) << 2) | 2ULL);
            sh_prefix = exc;
        }
    }
    __syncthreads();
    int pre = (int)sh_prefix;
    if (i < N_NODES) {
        int off = pre + incl - c;
        g_offset[i] = off;
        g_cursor[i] = off;
    }
    if (i == 0) g_offset[N_NODES] = N_EDGES;
}

// ---------------- K4: bucket edges by dst + reset lookback state -------------
__global__ void k_scatter(const int* __restrict__ ei) {
    if (blockIdx.x == 0) {
        if (threadIdx.x < N_SCAN_BLOCKS) g_state[threadIdx.x] = 0ULL;
        if (threadIdx.x == 0) g_ticket = 0;
    }
    int e = blockIdx.x * blockDim.x + threadIdx.x;
    if (e < N_EDGES) {
        int src = ei[e];
        int dst = ei[N_EDGES + e];
        int pos = atomicAdd(&g_cursor[dst], 1);
        g_srcsorted[pos] = src;
    }
}

// ---------------- K5: softmax + aggregation (half-warp per edge) -------------
// 16 lanes cover one edge's 128-half h row via uint4 (LDG.128); two edges per
// warp instruction; cross-half combine with one shfl_xor(16) pass at the end.
__global__ void __launch_bounds__(256) k_aggregate(float* __restrict__ out)
{
    int warp = threadIdx.x >> 5;
    int lane = threadIdx.x & 31;
    int n = blockIdx.x * 8 + warp;
    if (n >= N_NODES) return;

    int half = lane >> 4;            // which edge of the pair
    int sub  = lane & 15;            // 16 lanes x 8 halves = 128 halves
    int head = sub >> 2;

    int beg = g_offset[n];
    int end = g_offset[n + 1];

    float4 edn = *(const float4*)&g_ed[n * HEADS];
    float edh = (head == 0) ? edn.x : (head == 1) ? edn.y : (head == 2) ? edn.z : edn.w;

    float acc[8];
    #pragma unroll
    for (int j = 0; j < 8; ++j) acc[j] = 0.f;
    float ssum = 0.f;

    for (int e = beg; e < end; e += 4) {
        int i0 = e + half;
        int i1 = e + 2 + half;
        bool v0 = i0 < end;
        bool v1 = i1 < end;
        int s0 = g_srcsorted[v0 ? i0 : beg];
        int s1 = g_srcsorted[v1 ? i1 : beg];
        float ev0 = g_es[s0 * HEADS + head] + edh;
        float ev1 = g_es[s1 * HEADS + head] + edh;
        uint4 u0 = *(const uint4*)&g_h16[s0 * HO + sub * 8];
        uint4 u1 = *(const uint4*)&g_h16[s1 * HO + sub * 8];
        ev0 = ev0 >= 0.f ? ev0 : NEG_SLOPE * ev0;
        ev1 = ev1 >= 0.f ? ev1 : NEG_SLOPE * ev1;
        float w0 = v0 ? __expf(ev0) : 0.f;
        float w1 = v1 ? __expf(ev1) : 0.f;
        ssum += w0 + w1;
        float2 f;
        f = __half22float2(*(__half2*)&u0.x); acc[0] = fmaf(w0, f.x, acc[0]); acc[1] = fmaf(w0, f.y, acc[1]);
        f = __half22float2(*(__half2*)&u0.y); acc[2] = fmaf(w0, f.x, acc[2]); acc[3] = fmaf(w0, f.y, acc[3]);
        f = __half22float2(*(__half2*)&u0.z); acc[4] = fmaf(w0, f.x, acc[4]); acc[5] = fmaf(w0, f.y, acc[5]);
        f = __half22float2(*(__half2*)&u0.w); acc[6] = fmaf(w0, f.x, acc[6]); acc[7] = fmaf(w0, f.y, acc[7]);
        f = __half22float2(*(__half2*)&u1.x); acc[0] = fmaf(w1, f.x, acc[0]); acc[1] = fmaf(w1, f.y, acc[1]);
        f = __half22float2(*(__half2*)&u1.y); acc[2] = fmaf(w1, f.x, acc[2]); acc[3] = fmaf(w1, f.y, acc[3]);
        f = __half22float2(*(__half2*)&u1.z); acc[4] = fmaf(w1, f.x, acc[4]); acc[5] = fmaf(w1, f.y, acc[5]);
        f = __half22float2(*(__half2*)&u1.w); acc[6] = fmaf(w1, f.x, acc[6]); acc[7] = fmaf(w1, f.y, acc[7]);
    }

    // combine the two halves
    #pragma unroll
    for (int j = 0; j < 8; ++j)
        acc[j] += __shfl_xor_sync(0xffffffffu, acc[j], 16);
    ssum += __shfl_xor_sync(0xffffffffu, ssum, 16);

    float inv = 1.0f / (ssum + EPS_F);
    if (half == 0) {
        float4 r0 = make_float4(acc[0] * inv, acc[1] * inv, acc[2] * inv, acc[3] * inv);
        float4 r1 = make_float4(acc[4] * inv, acc[5] * inv, acc[6] * inv, acc[7] * inv);
        *(float4*)&out[n * HO + sub * 8]     = r0;
        *(float4*)&out[n * HO + sub * 8 + 4] = r1;
    }
}

// ---------------- launch: fork CSR chain onto a side stream ------------------
extern "C" void kernel_launch(void* const* d_in, const int* in_sizes, int n_in,
                              void* d_out, int out_size)
{
    const float* x     = (const float*)d_in[0];
    const int*   ei    = (const int*)  d_in[1];
    const float* W     = (const float*)d_in[2];
    const float* a_src = (const float*)d_in[3];
    const float* a_dst = (const float*)d_in[4];
    float* out = (float*)d_out;

    cudaFuncSetAttribute(k_gemm, cudaFuncAttributeMaxDynamicSharedMemorySize,
                         SMEM_GEMM_BYTES);

    cudaStream_t s1;
    cudaStreamCreateWithFlags(&s1, cudaStreamNonBlocking);
    cudaEvent_t ev0, ev1;
    cudaEventCreateWithFlags(&ev0, cudaEventDisableTiming);
    cudaEventCreateWithFlags(&ev1, cudaEventDisableTiming);

    cudaEventRecord(ev0, 0);
    cudaStreamWaitEvent(s1, ev0, 0);

    // side chain: CSR build (independent of GEMM)
    k_hist   <<<NB_HIST, 256, 0, s1>>>(ei);
    k_scanlb <<<N_SCAN_BLOCKS, SCAN_B, 0, s1>>>();
    k_scatter<<<(N_EDGES + 255) / 256, 256, 0, s1>>>(ei);
    cudaEventRecord(ev1, s1);

    // main stream: W pre-split, then projection GEMM (+logits)
    k_prep<<<(HEADS * IN_F * OUT_F + 255) / 256, 256>>>(W);
    k_gemm<<<NB_GEMM, 512, SMEM_GEMM_BYTES>>>(x, a_src, a_dst);

    // join, then aggregate
    cudaStreamWaitEvent(0, ev1, 0);
    k_aggregate<<<(N_NODES + 7) / 8, 256>>>(out);

    cudaEventDestroy(ev0);
    cudaEventDestroy(ev1);
    cudaStreamDestroy(s1);
}

// round 13
// speedup vs baseline: 1.0735x; 1.0384x over previous
#include <cuda_runtime.h>
#include <cuda_fp16.h>
#include <cuda_bf16.h>
#include <math.h>
#include <stdint.h>

#define N_NODES 50000
#define N_EDGES 800000
#define IN_F    128
#define OUT_F   32
#define HEADS   4
#define HO      128            // HEADS * OUT_F
#define NEG_SLOPE 0.2f
#define EPS_F 1e-10f

#define SCAN_B 256
#define N_SCAN_BLOCKS ((N_NODES + SCAN_B - 1) / SCAN_B)   // 196

#define BM 256
#define NB_GEMM ((N_NODES + BM - 1) / BM)                 // 196
#define NB_HIST ((N_EDGES + 255) / 256)                   // 3125

// smem: X planes [256][136] bf16 (hi/lo) + W planes [128][136] bf16 (hi/lo)
#define SM_STRIDE 136
#define SMX_PLANE (256 * SM_STRIDE)                       // 34816 halves
#define SMW_PLANE (128 * SM_STRIDE)                       // 17408 halves
#define SMEM_GEMM_BYTES ((2 * SMX_PLANE + 2 * SMW_PLANE) * 2)   // 208896
#define W_UINT4   (2 * SMW_PLANE * 2 / 16)                // 4352 uint4

// ---------------- scratch (static device allocations) ----------------------
__device__ __half g_h16[N_NODES * HO];     // projected features, fp16 [N, H*O]
__device__ float g_es[N_NODES * HEADS];    // per-node src logits (fp32)
__device__ float g_ed[N_NODES * HEADS];    // per-node dst logits (fp32)
__device__ __align__(16) __nv_bfloat16 g_Wsplit[2 * SMW_PLANE]; // Whi|Wlo image
__device__ int   g_count[N_NODES];         // zeroed at load; re-zeroed by scan
__device__ int   g_offset[N_NODES + 1];
__device__ int   g_cursor[N_NODES];
__device__ int   g_srcsorted[N_EDGES];
// decoupled-lookback state (zeroed at load; re-zeroed by k_scatter)
__device__ int                g_ticket;
__device__ unsigned long long g_state[N_SCAN_BLOCKS];   // (sum<<2)|status

// ---------------- bf16 mma helper ------------------------------------------
__device__ __forceinline__ void mma_bf16(float c[4],
    uint32_t a0, uint32_t a1, uint32_t a2, uint32_t a3,
    uint32_t b0, uint32_t b1)
{
    asm volatile(
        "mma.sync.aligned.m16n8k16.row.col.f32.bf16.bf16.f32 "
        "{%0,%1,%2,%3},{%4,%5,%6,%7},{%8,%9},{%0,%1,%2,%3};\n"
        : "+f"(c[0]), "+f"(c[1]), "+f"(c[2]), "+f"(c[3])
        : "r"(a0), "r"(a1), "r"(a2), "r"(a3), "r"(b0), "r"(b1));
}

// ---------------- K0: split W once into the swizzled smem image -------------
__global__ void k_prep(const float* __restrict__ W) {
    int idx = blockIdx.x * blockDim.x + threadIdx.x;     // 0..16383
    if (idx >= HEADS * IN_F * OUT_F) return;
    int o = idx & 31;
    int k = (idx >> 5) & 127;
    int n = (idx >> 12) * 32 + o;
    int ks = k ^ ((n & 3) << 4);
    float v = W[idx];
    __nv_bfloat16 hb = __float2bfloat16_rn(v);
    __nv_bfloat16 lb = __float2bfloat16_rn(v - __bfloat162float(hb));
    g_Wsplit[n * SM_STRIDE + ks] = hb;
    g_Wsplit[SMW_PLANE + n * SM_STRIDE + ks] = lb;
}

// ---------------- K1: bf16x3 tensor GEMM h = x @ Wc + fused logits ----------
// 512 thr = 16 warps in 8x2 grid; block tile 256x128; warp tile 32x64.
__global__ void __launch_bounds__(512) k_gemm(
    const float* __restrict__ x,
    const float* __restrict__ a_src,
    const float* __restrict__ a_dst)
{
    extern __shared__ __nv_bfloat16 sm[];
    __nv_bfloat16* Xhi = sm;
    __nv_bfloat16* Xlo = sm + SMX_PLANE;
    __nv_bfloat16* Whi = sm + 2 * SMX_PLANE;              // [n][k], swizzled
    __nv_bfloat16* Wlo = sm + 2 * SMX_PLANE + SMW_PLANE;

    int tid  = threadIdx.x;
    int w    = tid >> 5;
    int lane = tid & 31;
    int g    = lane >> 2;
    int t    = lane & 3;
    int wm   = w >> 1;       // warp row 0..7 (32 rows each)
    int wn   = w & 1;        // warp col 0..1 (64 cols each)
    int m0   = blockIdx.x * BM;

    // ---- stage X (256 rows x 128 k), split to bf16 hi/lo ----
    #pragma unroll
    for (int i = 0; i < 16; ++i) {
        int f = tid + i * 512;          // float4 id, 0..8191
        int r = f >> 5;
        int c = (f & 31) * 4;
        int grow = m0 + r;
        float4 v = make_float4(0.f, 0.f, 0.f, 0.f);
        if (grow < N_NODES) v = *(const float4*)&x[grow * IN_F + c];
        float vv[4] = {v.x, v.y, v.z, v.w};
        __nv_bfloat16 hb[4], lb[4];
        #pragma unroll
        for (int j = 0; j < 4; ++j) {
            hb[j] = __float2bfloat16_rn(vv[j]);
            lb[j] = __float2bfloat16_rn(vv[j] - __bfloat162float(hb[j]));
        }
        __nv_bfloat162 ph0(hb[0], hb[1]), ph1(hb[2], hb[3]);
        __nv_bfloat162 pl0(lb[0], lb[1]), pl1(lb[2], lb[3]);
        uint2 uh = make_uint2(reinterpret_cast<uint32_t&>(ph0),
                              reinterpret_cast<uint32_t&>(ph1));
        uint2 ul = make_uint2(reinterpret_cast<uint32_t&>(pl0),
                              reinterpret_cast<uint32_t&>(pl1));
        *(uint2*)&Xhi[r * SM_STRIDE + c] = uh;
        *(uint2*)&Xlo[r * SM_STRIDE + c] = ul;
    }
    // ---- bulk-copy the pre-split W image (70 KB, L2-resident) ----
    {
        const uint4* src = (const uint4*)g_Wsplit;
        uint4* dst = (uint4*)Whi;
        #pragma unroll
        for (int i = 0; i < 9; ++i) {
            int f = tid + i * 512;
            if (f < W_UINT4) dst[f] = src[f];
        }
    }
    __syncthreads();

    float C[2][8][4];
    #pragma unroll
    for (int ms = 0; ms < 2; ++ms)
        #pragma unroll
        for (int nt = 0; nt < 8; ++nt)
            #pragma unroll
            for (int j = 0; j < 4; ++j) C[ms][nt][j] = 0.0f;

    // ---- mainloop: 8 k-chunks of 16; LDS + MMA only ----
    #pragma unroll
    for (int kc = 0; kc < 8; ++kc) {
        int kw = kc * 8 + t;            // uint32 (bf16x2) index
        uint32_t axh[2][4], axl[2][4];
        #pragma unroll
        for (int ms = 0; ms < 2; ++ms) {
            int r0 = wm * 32 + ms * 16 + g;
            const uint32_t* ph0 = (const uint32_t*)(Xhi + r0 * SM_STRIDE);
            const uint32_t* ph8 = (const uint32_t*)(Xhi + (r0 + 8) * SM_STRIDE);
            const uint32_t* pl0 = (const uint32_t*)(Xlo + r0 * SM_STRIDE);
            const uint32_t* pl8 = (const uint32_t*)(Xlo + (r0 + 8) * SM_STRIDE);
            axh[ms][0] = ph0[kw];     axh[ms][1] = ph8[kw];
            axh[ms][2] = ph0[kw + 4]; axh[ms][3] = ph8[kw + 4];
            axl[ms][0] = pl0[kw];     axl[ms][1] = pl8[kw];
            axl[ms][2] = pl0[kw + 4]; axl[ms][3] = pl8[kw + 4];
        }
        #pragma unroll
        for (int nt = 0; nt < 8; ++nt) {
            int n = wn * 64 + nt * 8 + g;
            int kws = kw ^ ((n & 3) << 3);     // swizzled word index
            const uint32_t* qh = (const uint32_t*)(Whi + n * SM_STRIDE);
            const uint32_t* ql = (const uint32_t*)(Wlo + n * SM_STRIDE);
            uint32_t bh0 = qh[kws], bh1 = qh[kws + 4];
            uint32_t bl0 = ql[kws], bl1 = ql[kws + 4];
            #pragma unroll
            for (int ms = 0; ms < 2; ++ms) {
                mma_bf16(C[ms][nt], axh[ms][0], axh[ms][1], axh[ms][2], axh[ms][3], bh0, bh1);
                mma_bf16(C[ms][nt], axh[ms][0], axh[ms][1], axh[ms][2], axh[ms][3], bl0, bl1);
                mma_bf16(C[ms][nt], axl[ms][0], axl[ms][1], axl[ms][2], axl[ms][3], bh0, bh1);
            }
        }
    }

    // ---- epilogue: fp16 h store + fused per-head logits ----
    float psA[2][2], pdA[2][2], psB[2][2], pdB[2][2];
    #pragma unroll
    for (int ms = 0; ms < 2; ++ms)
        #pragma unroll
        for (int hl = 0; hl < 2; ++hl)
            psA[ms][hl] = pdA[ms][hl] = psB[ms][hl] = pdB[ms][hl] = 0.f;

    #pragma unroll
    for (int nt = 0; nt < 8; ++nt) {
        int hl = nt >> 2;
        int c0 = wn * 64 + nt * 8 + 2 * t;
        float as0 = a_src[c0], as1 = a_src[c0 + 1];
        float ad0 = a_dst[c0], ad1 = a_dst[c0 + 1];
        #pragma unroll
        for (int ms = 0; ms < 2; ++ms) {
            int row0 = m0 + wm * 32 + ms * 16 + g;
            psA[ms][hl] += C[ms][nt][0] * as0 + C[ms][nt][1] * as1;
            pdA[ms][hl] += C[ms][nt][0] * ad0 + C[ms][nt][1] * ad1;
            psB[ms][hl] += C[ms][nt][2] * as0 + C[ms][nt][3] * as1;
            pdB[ms][hl] += C[ms][nt][2] * ad0 + C[ms][nt][3] * ad1;
            if (row0 < N_NODES)
                *(__half2*)&g_h16[row0 * HO + c0] =
                    __floats2half2_rn(C[ms][nt][0], C[ms][nt][1]);
            if (row0 + 8 < N_NODES)
                *(__half2*)&g_h16[(row0 + 8) * HO + c0] =
                    __floats2half2_rn(C[ms][nt][2], C[ms][nt][3]);
        }
    }
    #pragma unroll
    for (int ms = 0; ms < 2; ++ms)
        #pragma unroll
        for (int hl = 0; hl < 2; ++hl) {
            psA[ms][hl] += __shfl_xor_sync(0xffffffffu, psA[ms][hl], 1);
            psA[ms][hl] += __shfl_xor_sync(0xffffffffu, psA[ms][hl], 2);
            pdA[ms][hl] += __shfl_xor_sync(0xffffffffu, pdA[ms][hl], 1);
            pdA[ms][hl] += __shfl_xor_sync(0xffffffffu, pdA[ms][hl], 2);
            psB[ms][hl] += __shfl_xor_sync(0xffffffffu, psB[ms][hl], 1);
            psB[ms][hl] += __shfl_xor_sync(0xffffffffu, psB[ms][hl], 2);
            pdB[ms][hl] += __shfl_xor_sync(0xffffffffu, pdB[ms][hl], 1);
            pdB[ms][hl] += __shfl_xor_sync(0xffffffffu, pdB[ms][hl], 2);
        }
    if (t == 0) {
        #pragma unroll
        for (int ms = 0; ms < 2; ++ms) {
            int row0 = m0 + wm * 32 + ms * 16 + g;
            int row1 = row0 + 8;
            if (row0 < N_NODES) {
                *(float2*)&g_es[row0 * HEADS + wn * 2] = make_float2(psA[ms][0], psA[ms][1]);
                *(float2*)&g_ed[row0 * HEADS + wn * 2] = make_float2(pdA[ms][0], pdA[ms][1]);
            }
            if (row1 < N_NODES) {
                *(float2*)&g_es[row1 * HEADS + wn * 2] = make_float2(psB[ms][0], psB[ms][1]);
                *(float2*)&g_ed[row1 * HEADS + wn * 2] = make_float2(pdB[ms][0], pdB[ms][1]);
            }
        }
    }
}

// ---------------- K2: degree histogram (side stream) ------------------------
__global__ void k_hist(const int* __restrict__ ei) {
    int e = blockIdx.x * blockDim.x + threadIdx.x;
    if (e < N_EDGES) atomicAdd(&g_count[ei[N_EDGES + e]], 1);
}

// ---------------- K3: single-kernel decoupled-lookback scan ------------------
__global__ void __launch_bounds__(SCAN_B) k_scanlb() {
    __shared__ int warp_sums[8];
    __shared__ int sh_bid;
    __shared__ long long sh_prefix;

    if (threadIdx.x == 0) sh_bid = atomicAdd(&g_ticket, 1);
    __syncthreads();
    int bid = sh_bid;

    int i = bid * SCAN_B + threadIdx.x;
    int lane = threadIdx.x & 31, wid = threadIdx.x >> 5;
    int c = (i < N_NODES) ? g_count[i] : 0;
    if (i < N_NODES) g_count[i] = 0;             // restore for next replay
    int v = c;
    #pragma unroll
    for (int d = 1; d < 32; d <<= 1) {
        int u = __shfl_up_sync(0xffffffffu, v, d);
        if (lane >= d) v += u;
    }
    if (lane == 31) warp_sums[wid] = v;
    __syncthreads();
    if (wid == 0) {
        int s = (lane < 8) ? warp_sums[lane] : 0;
        #pragma unroll
        for (int d = 1; d < 8; d <<= 1) {
            int u = __shfl_up_sync(0xffffffffu, s, d);
            if (lane >= d) s += u;
        }
        if (lane < 8) warp_sums[lane] = s;
    }
    __syncthreads();
    int incl = v + (wid ? warp_sums[wid - 1] : 0);
    long long T = warp_sums[7];

    if (threadIdx.x == 0) {
        if (bid == 0) {
            atomicExch(&g_state[0], ((unsigned long long)T << 2) | 2ULL);
            sh_prefix = 0;
        } else {
            atomicExch(&g_state[bid], ((unsigned long long)T << 2) | 1ULL);
            long long exc = 0;
            int pred = bid - 1;
            while (pred >= 0) {
                unsigned long long s;
                do { s = atomicAdd(&g_state[pred], 0ULL); } while ((s & 3ULL) == 0ULL);
                exc += (long long)(s >> 2);
                if ((s & 3ULL) == 2ULL) break;
                --pred;
            }
            atomicExch(&g_state[bid], ((unsigned long long)(exc + T) << 2) | 2ULL);
            sh_prefix = exc;
        }
    }
    __syncthreads();
    int pre = (int)sh_prefix;
    if (i < N_NODES) {
        int off = pre + incl - c;
        g_offset[i] = off;
        g_cursor[i] = off;
    }
    if (i == 0) g_offset[N_NODES] = N_EDGES;
}

// ---------------- K4: bucket edges by dst + reset lookback state -------------
__global__ void k_scatter(const int* __restrict__ ei) {
    if (blockIdx.x == 0) {
        if (threadIdx.x < N_SCAN_BLOCKS) g_state[threadIdx.x] = 0ULL;
        if (threadIdx.x == 0) g_ticket = 0;
    }
    int e = blockIdx.x * blockDim.x + threadIdx.x;
    if (e < N_EDGES) {
        int src = ei[e];
        int dst = ei[N_EDGES + e];
        int pos = atomicAdd(&g_cursor[dst], 1);
        g_srcsorted[pos] = src;
    }
}

// ---------------- K5: softmax + aggregation (half-warp per edge) -------------
// R11 known-good version: 16 lanes per edge, uint4 h loads, 2 pairs per iter.
__global__ void __launch_bounds__(256) k_aggregate(float* __restrict__ out)
{
    int warp = threadIdx.x >> 5;
    int lane = threadIdx.x & 31;
    int n = blockIdx.x * 8 + warp;
    if (n >= N_NODES) return;

    int half = lane >> 4;            // which edge of the pair
    int sub  = lane & 15;            // 16 lanes x 8 halves = 128 halves
    int head = sub >> 2;

    int beg = g_offset[n];
    int end = g_offset[n + 1];

    float4 edn = *(const float4*)&g_ed[n * HEADS];
    float edh = (head == 0) ? edn.x : (head == 1) ? edn.y : (head == 2) ? edn.z : edn.w;

    float acc[8];
    #pragma unroll
    for (int j = 0; j < 8; ++j) acc[j] = 0.f;
    float ssum = 0.f;

    for (int e = beg; e < end; e += 4) {
        int i0 = e + half;
        int i1 = e + 2 + half;
        bool v0 = i0 < end;
        bool v1 = i1 < end;
        int s0 = g_srcsorted[v0 ? i0 : beg];
        int s1 = g_srcsorted[v1 ? i1 : beg];
        float ev0 = g_es[s0 * HEADS + head] + edh;
        float ev1 = g_es[s1 * HEADS + head] + edh;
        uint4 u0 = *(const uint4*)&g_h16[s0 * HO + sub * 8];
        uint4 u1 = *(const uint4*)&g_h16[s1 * HO + sub * 8];
        ev0 = ev0 >= 0.f ? ev0 : NEG_SLOPE * ev0;
        ev1 = ev1 >= 0.f ? ev1 : NEG_SLOPE * ev1;
        float w0 = v0 ? __expf(ev0) : 0.f;
        float w1 = v1 ? __expf(ev1) : 0.f;
        ssum += w0 + w1;
        float2 f;
        f = __half22float2(*(__half2*)&u0.x); acc[0] = fmaf(w0, f.x, acc[0]); acc[1] = fmaf(w0, f.y, acc[1]);
        f = __half22float2(*(__half2*)&u0.y); acc[2] = fmaf(w0, f.x, acc[2]); acc[3] = fmaf(w0, f.y, acc[3]);
        f = __half22float2(*(__half2*)&u0.z); acc[4] = fmaf(w0, f.x, acc[4]); acc[5] = fmaf(w0, f.y, acc[5]);
        f = __half22float2(*(__half2*)&u0.w); acc[6] = fmaf(w0, f.x, acc[6]); acc[7] = fmaf(w0, f.y, acc[7]);
        f = __half22float2(*(__half2*)&u1.x); acc[0] = fmaf(w1, f.x, acc[0]); acc[1] = fmaf(w1, f.y, acc[1]);
        f = __half22float2(*(__half2*)&u1.y); acc[2] = fmaf(w1, f.x, acc[2]); acc[3] = fmaf(w1, f.y, acc[3]);
        f = __half22float2(*(__half2*)&u1.z); acc[4] = fmaf(w1, f.x, acc[4]); acc[5] = fmaf(w1, f.y, acc[5]);
        f = __half22float2(*(__half2*)&u1.w); acc[6] = fmaf(w1, f.x, acc[6]); acc[7] = fmaf(w1, f.y, acc[7]);
    }

    // combine the two halves
    #pragma unroll
    for (int j = 0; j < 8; ++j)
        acc[j] += __shfl_xor_sync(0xffffffffu, acc[j], 16);
    ssum += __shfl_xor_sync(0xffffffffu, ssum, 16);

    float inv = 1.0f / (ssum + EPS_F);
    if (half == 0) {
        float4 r0 = make_float4(acc[0] * inv, acc[1] * inv, acc[2] * inv, acc[3] * inv);
        float4 r1 = make_float4(acc[4] * inv, acc[5] * inv, acc[6] * inv, acc[7] * inv);
        *(float4*)&out[n * HO + sub * 8]     = r0;
        *(float4*)&out[n * HO + sub * 8 + 4] = r1;
    }
}

// ---------------- launch ------------------------------------------------------
// Launch order chosen so k_gemm is the 4th cudaLaunchKernel call (ncu slot).
extern "C" void kernel_launch(void* const* d_in, const int* in_sizes, int n_in,
                              void* d_out, int out_size)
{
    const float* x     = (const float*)d_in[0];
    const int*   ei    = (const int*)  d_in[1];
    const float* W     = (const float*)d_in[2];
    const float* a_src = (const float*)d_in[3];
    const float* a_dst = (const float*)d_in[4];
    float* out = (float*)d_out;

    cudaFuncSetAttribute(k_gemm, cudaFuncAttributeMaxDynamicSharedMemorySize,
                         SMEM_GEMM_BYTES);

    cudaStream_t s1;
    cudaStreamCreateWithFlags(&s1, cudaStreamNonBlocking);
    cudaEvent_t ev0, ev1;
    cudaEventCreateWithFlags(&ev0, cudaEventDisableTiming);
    cudaEventCreateWithFlags(&ev1, cudaEventDisableTiming);

    // launch 1: W pre-split (main)
    k_prep<<<(HEADS * IN_F * OUT_F + 255) / 256, 256>>>(W);

    cudaEventRecord(ev0, 0);
    cudaStreamWaitEvent(s1, ev0, 0);

    // launches 2-3: CSR build start (side stream)
    k_hist  <<<NB_HIST, 256, 0, s1>>>(ei);
    k_scanlb<<<N_SCAN_BLOCKS, SCAN_B, 0, s1>>>();

    // launch 4: projection GEMM (+logits) — profiled slot
    k_gemm<<<NB_GEMM, 512, SMEM_GEMM_BYTES>>>(x, a_src, a_dst);

    // launch 5: finish CSR build (side stream; queued after scanlb on s1)
    k_scatter<<<(N_EDGES + 255) / 256, 256, 0, s1>>>(ei);
    cudaEventRecord(ev1, s1);

    // join, then launch 6: aggregate
    cudaStreamWaitEvent(0, ev1, 0);
    k_aggregate<<<(N_NODES + 7) / 8, 256>>>(out);

    cudaEventDestroy(ev0);
    cudaEventDestroy(ev1);
    cudaStreamDestroy(s1);
}